// round 7
// baseline (speedup 1.0000x reference)
#include <cuda_runtime.h>
#include <cstdint>

#define N_NODES 50000
#define N_EDGES 800000
#define N_GRAPHS 64
#define HID 64
#define HEADS 4
#define LAT 32
#define FEAT 256   // HEADS*HID

// ---------------- scratch (device globals; no allocation) ----------------
__device__ float    g_xl[N_NODES * FEAT];      // 51.2 MB
__device__ float    g_xr[N_NODES * FEAT];      // 51.2 MB
__device__ float    g_h[N_NODES * HID];        // current node features
__device__ float    g_hnext[N_NODES * HID];    // accumulated layer output
__device__ float    g_logits[N_EDGES * HEADS]; // logits, then p=exp(logit-max)
__device__ unsigned g_maxenc[N_NODES * HEADS]; // order-encoded segment max
__device__ float    g_denom[N_NODES * HEADS];  // softmax denominators
__device__ int      g_src[N_EDGES];
__device__ int      g_dst[N_EDGES];
__device__ float    g_pooled[N_GRAPHS * HID];

// Order-preserving float<->uint encoding so atomicMax(uint) == float max.
// enc is strictly increasing; memset(0) < enc(-inf), so 0 acts as -infinity.
__device__ __forceinline__ unsigned encf(float f) {
    unsigned b = __float_as_uint(f);
    return (b & 0x80000000u) ? ~b : (b | 0x80000000u);
}
__device__ __forceinline__ float decf(unsigned u) {
    return __uint_as_float((u & 0x80000000u) ? (u & 0x7FFFFFFFu) : ~u);
}

// ---------------- prep: copy edge index (int32!), zero pooled ----------------
__global__ void prep_kernel(const int* __restrict__ ei) {
    int i = blockIdx.x * 256 + threadIdx.x;
    if (i < N_EDGES) {
        g_src[i] = ei[i];
        g_dst[i] = ei[N_EDGES + i];
    }
    if (i < N_GRAPHS * HID) g_pooled[i] = 0.f;
}

// ---------------- per-layer zero init ----------------
__global__ void zero_layer_kernel() {
    int i = blockIdx.x * 256 + threadIdx.x;
    if (i < N_NODES * HID) g_hnext[i] = 0.f;
    if (i < N_NODES * HEADS) { g_maxenc[i] = 0u; g_denom[i] = 0.f; }
}

// ---------------- GEMM: O = A @ W, A [N,K], W [K,256] ----------------
// blockIdx.y selects (Wl -> g_xl) vs (Wr -> g_xr).
// 256 threads = 64 col-groups x 4 row-groups; each thread: 8 rows x 4 cols.
template <int K>
__global__ void __launch_bounds__(256)
gemm_kernel(const float* __restrict__ xext, int use_h,
            const float* __restrict__ W0, const float* __restrict__ W1) {
    const float* __restrict__ A = use_h ? g_h : xext;
    const float* __restrict__ W = blockIdx.y ? W1 : W0;
    float* __restrict__ O = blockIdx.y ? g_xr : g_xl;

    __shared__ float sAT[K][36];  // [k][row], 32 rows padded to 36 (keeps 16B align)

    const int row0 = blockIdx.x * 32;
    const int tid = threadIdx.x;
    const int KQ = K / 4;

    for (int idx = tid; idx < 32 * KQ; idx += 256) {
        int r = idx / KQ, kq = idx % KQ;
        float4 v = make_float4(0.f, 0.f, 0.f, 0.f);
        if (row0 + r < N_NODES)
            v = *(const float4*)(A + (size_t)(row0 + r) * K + kq * 4);
        sAT[kq * 4 + 0][r] = v.x;
        sAT[kq * 4 + 1][r] = v.y;
        sAT[kq * 4 + 2][r] = v.z;
        sAT[kq * 4 + 3][r] = v.w;
    }
    __syncthreads();

    const int tx = tid & 63;   // cols [tx*4, tx*4+4)
    const int ty = tid >> 6;   // rows [ty*8, ty*8+8)

    float acc[8][4];
#pragma unroll
    for (int r = 0; r < 8; r++)
#pragma unroll
        for (int c = 0; c < 4; c++) acc[r][c] = 0.f;

    const float* __restrict__ Wc = W + tx * 4;
#pragma unroll 4
    for (int k = 0; k < K; k++) {
        float4 w = *(const float4*)(Wc + (size_t)k * FEAT);
        float4 alo = *(const float4*)(&sAT[k][ty * 8]);
        float4 ahi = *(const float4*)(&sAT[k][ty * 8 + 4]);
        float a[8] = {alo.x, alo.y, alo.z, alo.w, ahi.x, ahi.y, ahi.z, ahi.w};
#pragma unroll
        for (int r = 0; r < 8; r++) {
            acc[r][0] += a[r] * w.x;
            acc[r][1] += a[r] * w.y;
            acc[r][2] += a[r] * w.z;
            acc[r][3] += a[r] * w.w;
        }
    }

#pragma unroll
    for (int r = 0; r < 8; r++) {
        int row = row0 + ty * 8 + r;
        if (row < N_NODES)
            *(float4*)(O + (size_t)row * FEAT + tx * 4) =
                make_float4(acc[r][0], acc[r][1], acc[r][2], acc[r][3]);
    }
}

// ---------------- edge pass 1: logits + segment max ----------------
// one warp per edge; 8 lanes per head; lrelu(xl[src]+xr[dst], 0.2) . att
__global__ void __launch_bounds__(256)
edge_logits_kernel(const float* __restrict__ att) {
    int warp = (blockIdx.x * 256 + threadIdx.x) >> 5;
    if (warp >= N_EDGES) return;
    int lane = threadIdx.x & 31;
    int s = g_src[warp], d = g_dst[warp];
    const float4* __restrict__ pl = (const float4*)(g_xl + (size_t)s * FEAT);
    const float4* __restrict__ pr = (const float4*)(g_xr + (size_t)d * FEAT);
    const float4* __restrict__ pa = (const float4*)att;

    float sum = 0.f;
#pragma unroll
    for (int i = 0; i < 2; i++) {
        int j = lane * 2 + i;
        float4 a = pl[j], b = pr[j], t = pa[j];
        float ex = a.x + b.x; ex = ex > 0.f ? ex : 0.2f * ex;
        float ey = a.y + b.y; ey = ey > 0.f ? ey : 0.2f * ey;
        float ez = a.z + b.z; ez = ez > 0.f ? ez : 0.2f * ez;
        float ew = a.w + b.w; ew = ew > 0.f ? ew : 0.2f * ew;
        sum += ex * t.x + ey * t.y + ez * t.z + ew * t.w;
    }
    // reduce within each 8-lane group (one head per group)
    sum += __shfl_down_sync(0xffffffffu, sum, 4);
    sum += __shfl_down_sync(0xffffffffu, sum, 2);
    sum += __shfl_down_sync(0xffffffffu, sum, 1);
    if ((lane & 7) == 0) {
        int h = lane >> 3;
        g_logits[(size_t)warp * HEADS + h] = sum;
        atomicMax(&g_maxenc[d * HEADS + h], encf(sum));
    }
}

// ---------------- edge pass 2: p = exp(logit - max); segment sum ----------------
__global__ void edge_exp_kernel() {
    int i = blockIdx.x * 256 + threadIdx.x;
    if (i >= N_EDGES * HEADS) return;
    int e = i >> 2, h = i & 3;
    int d = g_dst[e];
    float m = decf(g_maxenc[d * HEADS + h]);
    float p = __expf(g_logits[i] - m);
    g_logits[i] = p;
    atomicAdd(&g_denom[d * HEADS + h], p);
}

// ---------------- edge pass 3: hnext[dst] += 0.25 * sum_h alpha_h * xl[src][h] ----
// one warp per edge; head-mean folded in -> 64 atomics/edge instead of 256
__global__ void __launch_bounds__(256)
edge_agg_kernel() {
    int warp = (blockIdx.x * 256 + threadIdx.x) >> 5;
    if (warp >= N_EDGES) return;
    int lane = threadIdx.x & 31;
    int s = g_src[warp], d = g_dst[warp];

    float al = 0.f;
    if (lane < 4) {
        float p = g_logits[(size_t)warp * HEADS + lane];
        float dn = g_denom[d * HEADS + lane];
        al = p / (dn + 1e-16f);
    }
    float a0 = __shfl_sync(0xffffffffu, al, 0);
    float a1 = __shfl_sync(0xffffffffu, al, 1);
    float a2 = __shfl_sync(0xffffffffu, al, 2);
    float a3 = __shfl_sync(0xffffffffu, al, 3);

    const float2* __restrict__ px = (const float2*)(g_xl + (size_t)s * FEAT);
    float2 v0 = px[lane], v1 = px[32 + lane], v2 = px[64 + lane], v3 = px[96 + lane];
    float r0 = 0.25f * (a0 * v0.x + a1 * v1.x + a2 * v2.x + a3 * v3.x);
    float r1 = 0.25f * (a0 * v0.y + a1 * v1.y + a2 * v2.y + a3 * v3.y);
    float* dstp = g_hnext + (size_t)d * HID + lane * 2;
    atomicAdd(dstp, r0);
    atomicAdd(dstp + 1, r1);
}

// ---------------- node epilogue: +bias, leaky_relu(0.1), optional pooling ----
__global__ void node_finish_kernel(const float* __restrict__ bias,
                                   const int* __restrict__ batch,
                                   int do_pool) {
    int i = blockIdx.x * 256 + threadIdx.x;
    if (i >= N_NODES * HID) return;
    int dch = i & 63;
    float v = g_hnext[i] + bias[dch];
    v = v > 0.f ? v : 0.1f * v;
    g_h[i] = v;
    if (do_pool) {
        int gph = batch[i >> 6];
        atomicAdd(&g_pooled[gph * HID + dch], v);
    }
}

// ---------------- BN over graphs + FC, single block ----------------
__global__ void bn_fc_kernel(const float* __restrict__ gamma,
                             const float* __restrict__ beta,
                             const float* __restrict__ fcW,
                             const float* __restrict__ fcb,
                             float* __restrict__ out) {
    __shared__ float snorm[N_GRAPHS * HID];
    int tid = threadIdx.x;
    if (tid < HID) {
        float s = 0.f;
        for (int g = 0; g < N_GRAPHS; g++) s += g_pooled[g * HID + tid];
        float mean = s * (1.f / N_GRAPHS);
        float vs = 0.f;
        for (int g = 0; g < N_GRAPHS; g++) {
            float dlt = g_pooled[g * HID + tid] - mean;
            vs += dlt * dlt;
        }
        float inv = rsqrtf(vs * (1.f / N_GRAPHS) + 1e-5f);
        float ga = gamma[tid] * inv, be = beta[tid];
        for (int g = 0; g < N_GRAPHS; g++)
            snorm[g * HID + tid] = (g_pooled[g * HID + tid] - mean) * ga + be;
    }
    __syncthreads();
    for (int i = tid; i < N_GRAPHS * LAT; i += blockDim.x) {
        int g = i >> 5, l = i & 31;
        float s = fcb[l];
#pragma unroll
        for (int d = 0; d < HID; d++) s += snorm[g * HID + d] * fcW[l * HID + d];
        out[i] = s;
    }
}

// ---------------- launch ----------------
extern "C" void kernel_launch(void* const* d_in, const int* in_sizes, int n_in,
                              void* d_out, int out_size) {
    const float* x = (const float*)d_in[0];
    const int* ei = (const int*)d_in[1];      // JAX x64 disabled: int64 -> int32
    const int* batch = (const int*)d_in[2];   // likewise int32
    const float* Wl[3]  = {(const float*)d_in[3],  (const float*)d_in[7],  (const float*)d_in[11]};
    const float* Wr[3]  = {(const float*)d_in[4],  (const float*)d_in[8],  (const float*)d_in[12]};
    const float* att[3] = {(const float*)d_in[5],  (const float*)d_in[9],  (const float*)d_in[13]};
    const float* bb[3]  = {(const float*)d_in[6],  (const float*)d_in[10], (const float*)d_in[14]};
    const float* gamma = (const float*)d_in[15];
    const float* beta  = (const float*)d_in[16];
    const float* fcW   = (const float*)d_in[17];
    const float* fcb   = (const float*)d_in[18];
    float* out = (float*)d_out;

    prep_kernel<<<(N_EDGES + 255) / 256, 256>>>(ei);

    const int gemm_bx = (N_NODES + 31) / 32;
    const int zero_b  = (N_NODES * HID + 255) / 256;
    const int elog_b  = N_EDGES / 8;                 // one warp per edge
    const int eexp_b  = (N_EDGES * HEADS + 255) / 256;
    const int node_b  = (N_NODES * HID + 255) / 256;

    for (int l = 0; l < 3; l++) {
        dim3 ggrid(gemm_bx, 2);
        if (l == 0) gemm_kernel<128><<<ggrid, 256>>>(x, 0, Wl[0], Wr[0]);
        else        gemm_kernel<64><<<ggrid, 256>>>(nullptr, 1, Wl[l], Wr[l]);

        zero_layer_kernel<<<zero_b, 256>>>();
        edge_logits_kernel<<<elog_b, 256>>>(att[l]);
        edge_exp_kernel<<<eexp_b, 256>>>();
        edge_agg_kernel<<<elog_b, 256>>>();
        node_finish_kernel<<<node_b, 256>>>(bb[l], batch, l == 2 ? 1 : 0);
    }

    bn_fc_kernel<<<1, 256>>>(gamma, beta, fcW, fcb, out);
}

// round 8
// speedup vs baseline: 1.2545x; 1.2545x over previous
#include <cuda_runtime.h>
#include <cstdint>

#define N_NODES 50000
#define N_EDGES 800000
#define N_GRAPHS 64
#define HID 64
#define HEADS 4
#define LAT 32
#define FEAT 256   // HEADS*HID

// ---------------- scratch (device globals; no allocation) ----------------
__device__ float g_xl[N_NODES * FEAT];      // 51.2 MB
__device__ float g_xr[N_NODES * FEAT];      // 51.2 MB
__device__ float g_h[N_NODES * HID];        // current node features
__device__ int   g_src[N_EDGES];
__device__ int   g_dst[N_EDGES];
__device__ int   g_esrc[N_EDGES];           // src ids, edges sorted by dst
__device__ int   g_deg[N_NODES];
__device__ int   g_scan[49 * 1024];         // 50176 >= N_NODES
__device__ int   g_bsum[64];
__device__ int   g_boff[64];
__device__ int   g_off[N_NODES + 1];        // CSR offsets by dst
__device__ int   g_cur[N_NODES];            // scatter cursors
__device__ float g_pooled[N_GRAPHS * HID];

// ---------------- prep: copy edge index, zero deg/pooled ----------------
__global__ void prep_kernel(const int* __restrict__ ei) {
    int i = blockIdx.x * 256 + threadIdx.x;
    if (i < N_EDGES) {
        g_src[i] = ei[i];
        g_dst[i] = ei[N_EDGES + i];
    }
    if (i < N_NODES) g_deg[i] = 0;
    if (i < N_GRAPHS * HID) g_pooled[i] = 0.f;
}

__global__ void hist_kernel() {
    int i = blockIdx.x * 256 + threadIdx.x;
    if (i < N_EDGES) atomicAdd(&g_deg[g_dst[i]], 1);
}

// ---- 3-kernel scan over g_deg -> g_off (exclusive), g_cur = g_off ----
__global__ void scan1_kernel() {
    __shared__ int sm[1024];
    int t = threadIdx.x, i = blockIdx.x * 1024 + t;
    int v = (i < N_NODES) ? g_deg[i] : 0;
    sm[t] = v;
    __syncthreads();
    for (int ofs = 1; ofs < 1024; ofs <<= 1) {
        int x = (t >= ofs) ? sm[t - ofs] : 0;
        __syncthreads();
        sm[t] += x;
        __syncthreads();
    }
    g_scan[i] = sm[t];
    if (t == 1023) g_bsum[blockIdx.x] = sm[1023];
}

__global__ void scan2_kernel() {
    __shared__ int sm[64];
    int t = threadIdx.x;
    int v = (t < 49) ? g_bsum[t] : 0;
    sm[t] = v;
    __syncthreads();
    for (int ofs = 1; ofs < 64; ofs <<= 1) {
        int x = (t >= ofs) ? sm[t - ofs] : 0;
        __syncthreads();
        sm[t] += x;
        __syncthreads();
    }
    g_boff[t] = sm[t] - v;   // exclusive block offset
}

__global__ void scan3_kernel() {
    int i = blockIdx.x * 256 + threadIdx.x;
    if (i >= N_NODES) return;
    g_off[i + 1] = g_scan[i] + g_boff[i >> 10];
    int o = (i == 0) ? 0 : (g_scan[i - 1] + g_boff[(i - 1) >> 10]);
    g_cur[i] = o;
    if (i == 0) g_off[0] = 0;
}

__global__ void scatter_kernel() {
    int e = blockIdx.x * 256 + threadIdx.x;
    if (e >= N_EDGES) return;
    int d = g_dst[e];
    int pos = atomicAdd(&g_cur[d], 1);
    g_esrc[pos] = g_src[e];
}

// ---------------- GEMM: O = A @ W, A [N,K], W [K,256] ----------------
template <int K>
__global__ void __launch_bounds__(256)
gemm_kernel(const float* __restrict__ xext, int use_h,
            const float* __restrict__ W0, const float* __restrict__ W1) {
    const float* __restrict__ A = use_h ? g_h : xext;
    const float* __restrict__ W = blockIdx.y ? W1 : W0;
    float* __restrict__ O = blockIdx.y ? g_xr : g_xl;

    __shared__ float sAT[K][36];

    const int row0 = blockIdx.x * 32;
    const int tid = threadIdx.x;
    const int KQ = K / 4;

    for (int idx = tid; idx < 32 * KQ; idx += 256) {
        int r = idx / KQ, kq = idx % KQ;
        float4 v = make_float4(0.f, 0.f, 0.f, 0.f);
        if (row0 + r < N_NODES)
            v = *(const float4*)(A + (size_t)(row0 + r) * K + kq * 4);
        sAT[kq * 4 + 0][r] = v.x;
        sAT[kq * 4 + 1][r] = v.y;
        sAT[kq * 4 + 2][r] = v.z;
        sAT[kq * 4 + 3][r] = v.w;
    }
    __syncthreads();

    const int tx = tid & 63;
    const int ty = tid >> 6;

    float acc[8][4];
#pragma unroll
    for (int r = 0; r < 8; r++)
#pragma unroll
        for (int c = 0; c < 4; c++) acc[r][c] = 0.f;

    const float* __restrict__ Wc = W + tx * 4;
#pragma unroll 4
    for (int k = 0; k < K; k++) {
        float4 w = *(const float4*)(Wc + (size_t)k * FEAT);
        float4 alo = *(const float4*)(&sAT[k][ty * 8]);
        float4 ahi = *(const float4*)(&sAT[k][ty * 8 + 4]);
        float a[8] = {alo.x, alo.y, alo.z, alo.w, ahi.x, ahi.y, ahi.z, ahi.w};
#pragma unroll
        for (int r = 0; r < 8; r++) {
            acc[r][0] += a[r] * w.x;
            acc[r][1] += a[r] * w.y;
            acc[r][2] += a[r] * w.z;
            acc[r][3] += a[r] * w.w;
        }
    }

#pragma unroll
    for (int r = 0; r < 8; r++) {
        int row = row0 + ty * 8 + r;
        if (row < N_NODES)
            *(float4*)(O + (size_t)row * FEAT + tx * 4) =
                make_float4(acc[r][0], acc[r][1], acc[r][2], acc[r][3]);
    }
}

// ---------------- fused GATv2 layer: warp per dst node, online softmax ----
// lane = grp*8 + gl; grp = head, lane covers features [grp*64 + gl*8, +8)
__global__ void __launch_bounds__(256)
fused_gat_kernel(const float* __restrict__ att, const float* __restrict__ bias,
                 const int* __restrict__ batch, int do_pool) {
    int d = blockIdx.x * 8 + (threadIdx.x >> 5);
    if (d >= N_NODES) return;
    int lane = threadIdx.x & 31;
    int grp = lane >> 3, gl = lane & 7;
    int fb = grp * 64 + gl * 8;

    const float4* __restrict__ xr4 = (const float4*)(g_xr + (size_t)d * FEAT + fb);
    float4 r0 = xr4[0], r1 = xr4[1];
    const float4* __restrict__ at4 = (const float4*)(att + fb);
    float4 t0 = at4[0], t1 = at4[1];

    float m = -1e30f, s = 0.f;
    float acc[8];
#pragma unroll
    for (int i = 0; i < 8; i++) acc[i] = 0.f;

    int e0 = g_off[d], e1 = g_off[d + 1];
    for (int p = e0; p < e1; p++) {
        int sn = __ldg(&g_esrc[p]);
        const float4* __restrict__ xl4 = (const float4*)(g_xl + (size_t)sn * FEAT + fb);
        float4 a0 = xl4[0], a1 = xl4[1];

        float L;
        {
            float e, q = 0.f;
            e = a0.x + r0.x; e = e > 0.f ? e : 0.2f * e; q += e * t0.x;
            e = a0.y + r0.y; e = e > 0.f ? e : 0.2f * e; q += e * t0.y;
            e = a0.z + r0.z; e = e > 0.f ? e : 0.2f * e; q += e * t0.z;
            e = a0.w + r0.w; e = e > 0.f ? e : 0.2f * e; q += e * t0.w;
            e = a1.x + r1.x; e = e > 0.f ? e : 0.2f * e; q += e * t1.x;
            e = a1.y + r1.y; e = e > 0.f ? e : 0.2f * e; q += e * t1.y;
            e = a1.z + r1.z; e = e > 0.f ? e : 0.2f * e; q += e * t1.z;
            e = a1.w + r1.w; e = e > 0.f ? e : 0.2f * e; q += e * t1.w;
            L = q;
        }
        // per-head logit: reduce within the 8-lane group
        L += __shfl_xor_sync(0xffffffffu, L, 1);
        L += __shfl_xor_sync(0xffffffffu, L, 2);
        L += __shfl_xor_sync(0xffffffffu, L, 4);

        // online softmax update
        float mn = fmaxf(m, L);
        float sc = __expf(m - mn);
        float pw = __expf(L - mn);
        m = mn;
        s = s * sc + pw;
        acc[0] = acc[0] * sc + pw * a0.x;
        acc[1] = acc[1] * sc + pw * a0.y;
        acc[2] = acc[2] * sc + pw * a0.z;
        acc[3] = acc[3] * sc + pw * a0.w;
        acc[4] = acc[4] * sc + pw * a1.x;
        acc[5] = acc[5] * sc + pw * a1.y;
        acc[6] = acc[6] * sc + pw * a1.z;
        acc[7] = acc[7] * sc + pw * a1.w;
    }

    // per-head normalize + fold head-mean, then sum across heads
    float inv = 0.25f / (s + 1e-16f);
#pragma unroll
    for (int i = 0; i < 8; i++) {
        float v = acc[i] * inv;
        v += __shfl_xor_sync(0xffffffffu, v, 8);
        v += __shfl_xor_sync(0xffffffffu, v, 16);
        acc[i] = v;
    }

    if (grp == 0) {
        float out[8];
#pragma unroll
        for (int i = 0; i < 8; i++) {
            float v = acc[i] + bias[gl * 8 + i];
            out[i] = v > 0.f ? v : 0.1f * v;
        }
        float4* hp = (float4*)(g_h + (size_t)d * HID + gl * 8);
        hp[0] = make_float4(out[0], out[1], out[2], out[3]);
        hp[1] = make_float4(out[4], out[5], out[6], out[7]);
        if (do_pool) {
            int gph = batch[d];
            float* pp = g_pooled + gph * HID + gl * 8;
#pragma unroll
            for (int i = 0; i < 8; i++) atomicAdd(pp + i, out[i]);
        }
    }
}

// ---------------- BN over graphs + FC, single block ----------------
__global__ void bn_fc_kernel(const float* __restrict__ gamma,
                             const float* __restrict__ beta,
                             const float* __restrict__ fcW,
                             const float* __restrict__ fcb,
                             float* __restrict__ out) {
    __shared__ float snorm[N_GRAPHS * HID];
    int tid = threadIdx.x;
    if (tid < HID) {
        float s = 0.f;
        for (int g = 0; g < N_GRAPHS; g++) s += g_pooled[g * HID + tid];
        float mean = s * (1.f / N_GRAPHS);
        float vs = 0.f;
        for (int g = 0; g < N_GRAPHS; g++) {
            float dlt = g_pooled[g * HID + tid] - mean;
            vs += dlt * dlt;
        }
        float inv = rsqrtf(vs * (1.f / N_GRAPHS) + 1e-5f);
        float ga = gamma[tid] * inv, be = beta[tid];
        for (int g = 0; g < N_GRAPHS; g++)
            snorm[g * HID + tid] = (g_pooled[g * HID + tid] - mean) * ga + be;
    }
    __syncthreads();
    for (int i = tid; i < N_GRAPHS * LAT; i += blockDim.x) {
        int g = i >> 5, l = i & 31;
        float s = fcb[l];
#pragma unroll
        for (int d = 0; d < HID; d++) s += snorm[g * HID + d] * fcW[l * HID + d];
        out[i] = s;
    }
}

// ---------------- launch ----------------
extern "C" void kernel_launch(void* const* d_in, const int* in_sizes, int n_in,
                              void* d_out, int out_size) {
    const float* x = (const float*)d_in[0];
    const int* ei = (const int*)d_in[1];
    const int* batch = (const int*)d_in[2];
    const float* Wl[3]  = {(const float*)d_in[3],  (const float*)d_in[7],  (const float*)d_in[11]};
    const float* Wr[3]  = {(const float*)d_in[4],  (const float*)d_in[8],  (const float*)d_in[12]};
    const float* att[3] = {(const float*)d_in[5],  (const float*)d_in[9],  (const float*)d_in[13]};
    const float* bb[3]  = {(const float*)d_in[6],  (const float*)d_in[10], (const float*)d_in[14]};
    const float* gamma = (const float*)d_in[15];
    const float* beta  = (const float*)d_in[16];
    const float* fcW   = (const float*)d_in[17];
    const float* fcb   = (const float*)d_in[18];
    float* out = (float*)d_out;

    const int eb = (N_EDGES + 255) / 256;           // 3125
    prep_kernel<<<eb, 256>>>(ei);
    hist_kernel<<<eb, 256>>>();
    scan1_kernel<<<49, 1024>>>();
    scan2_kernel<<<1, 64>>>();
    scan3_kernel<<<(N_NODES + 255) / 256, 256>>>();
    scatter_kernel<<<eb, 256>>>();

    const int gemm_bx = (N_NODES + 31) / 32;
    const int gat_b = (N_NODES + 7) / 8;            // warp per node

    for (int l = 0; l < 3; l++) {
        dim3 ggrid(gemm_bx, 2);
        if (l == 0) gemm_kernel<128><<<ggrid, 256>>>(x, 0, Wl[0], Wr[0]);
        else        gemm_kernel<64><<<ggrid, 256>>>(nullptr, 1, Wl[l], Wr[l]);

        fused_gat_kernel<<<gat_b, 256>>>(att[l], bb[l], batch, l == 2 ? 1 : 0);
    }

    bn_fc_kernel<<<1, 256>>>(gamma, beta, fcW, fcb, out);
}